// round 11
// baseline (speedup 1.0000x reference)
#include <cuda_runtime.h>
#include <cmath>

// ---------------------------------------------------------------------------
// CTLNN persistent kernel, round 11: warp-specialized dual row-streams.
// 128 CTAs; each owns 4 H-columns (cbase = bid*4). Each CTA splits into two
// warpgroups of 256 threads: wg0 processes batch rows 0-31, wg1 rows 32-63,
// each with its OWN stage buffers, OWN distributed grid-barrier set, and
// bar.sync-scoped intra-wg synchronization. The two streams interleave on
// the SM, hiding each other's barrier + L2 staging latency.
// Per wg: threads (r:32, kp:8); each thread computes all 4 CTA columns over
// a K/8 slice. tau folded through the mapper (3 phases/step); LayerNorm
// folded into phase A; cp.async double-buffered staging; FFMA2 inner loops.
// ---------------------------------------------------------------------------

namespace {
constexpr int Tt   = 1024;
constexpr int DIN  = 256;
constexpr int Hh   = 512;
constexpr int NCTA = 128;
constexpr int NTHR = 512;
constexpr int NBAR = 16;
constexpr int BARSTRIDE = 32;
constexpr float DTc  = 0.01f;
constexpr float EPSc = 1e-5f;

// SMEM float offsets
constexpr int OFF_WMX   = 0;        // 8 x 256 (x-rows: 4 gate + 4 core cols)
constexpr int OFF_WMV   = 2048;     // 8 x 512 (h-rows, gamma-folded)
constexpr int OFF_WFX   = 6144;     // 4 x 256 tau x-fold
constexpr int OFF_WFV   = 7168;     // 4 x 512 tau v-fold (gamma-folded)
constexpr int OFF_WF1   = 9216;     // 4 x 512
constexpr int OFF_WF2   = 11264;    // 4 x 512
constexpr int OFF_STAGE = 13312;    // 4 buffers x 2048 float4 (32KB each)
constexpr int OFF_RED   = 46080;    // 2 wg x 768 float4
constexpr int OFF_B     = 52224;    // 64 consts
constexpr int OFF_RSTD  = 52288;    // 2 x 32
constexpr int SMEM_FLOATS = 52352;  // ~209.4 KB
// OFF_B: 0 bmg[4] 4 bmc[4] 8 tauC0[4] 12 bf1[4] 16 bf2[4] 20 gam[4] 24 bet[4]
//        28 Bsum[8] (g,core) 36 Gsum[8] 44 BsumT[4] 48 GsumT[4]
}

// Cross-CTA state
__device__ unsigned g_barArr[2][NBAR * BARSTRIDE];   // one set per row-stream
__device__ float g_rs[128], g_rq[128];               // [par][globalRow]
__device__ float g_v[64 * Hh];
__device__ float g_z[64 * Hh];
__device__ float g_a1[64 * Hh];

__global__ void ctlnn_reset() {
    int i = blockIdx.x * blockDim.x + threadIdx.x;
    if (i < 2 * NBAR * BARSTRIDE) (&g_barArr[0][0])[i] = 0u;
    if (i < 128) { g_rs[i] = 0.f; g_rq[i] = 0.f; }
    for (int k = i; k < 64 * Hh; k += gridDim.x * blockDim.x) g_v[k] = 0.f;
}

// ---- helpers --------------------------------------------------------------
__device__ __forceinline__ void cp16(float4* dst, const void* src) {
    unsigned s = (unsigned)__cvta_generic_to_shared(dst);
    asm volatile("cp.async.cg.shared.global [%0], [%1], 16;" :: "r"(s), "l"(src));
}
__device__ __forceinline__ void cp_commit() {
    asm volatile("cp.async.commit_group;" ::: "memory");
}
template <int N>
__device__ __forceinline__ void cp_wait() {
    asm volatile("cp.async.wait_group %0;" :: "n"(N) : "memory");
}
__device__ __forceinline__ void fma2(unsigned long long& d,
                                     unsigned long long a, unsigned long long b) {
    asm volatile("fma.rn.f32x2 %0, %1, %2, %3;" : "=l"(d) : "l"(a), "l"(b), "l"(d));
}
__device__ __forceinline__ unsigned long long mul2(unsigned long long a,
                                                   unsigned long long b) {
    unsigned long long d;
    asm("mul.rn.f32x2 %0, %1, %2;" : "=l"(d) : "l"(a), "l"(b));
    return d;
}
__device__ __forceinline__ float hsum(unsigned long long u) {
    float lo, hi;
    asm("mov.b64 {%0,%1}, %2;" : "=f"(lo), "=f"(hi) : "l"(u));
    return lo + hi;
}
// per-warpgroup sync (named barrier, 256 threads)
__device__ __forceinline__ void wg_sync(int wgid) {
    asm volatile("bar.sync %0, 256;" :: "r"(1 + wgid) : "memory");
}

// Distributed per-stream barrier.
__device__ __forceinline__ void bar_arrive(int s, int wtid, int wgid) {
    __threadfence();
    wg_sync(wgid);
    if (wtid == 0)
        atomicAdd(&g_barArr[s][(blockIdx.x & (NBAR - 1)) * BARSTRIDE], 1u);
}
__device__ __forceinline__ void bar_wait(int s, unsigned target8, int wtid,
                                         int wgid) {
    if (wtid < NBAR) {
        unsigned v;
        do {
            asm volatile("ld.global.acquire.gpu.u32 %0, [%1];"
                         : "=r"(v) : "l"(&g_barArr[s][wtid * BARSTRIDE]));
        } while (v < target8);
    }
    wg_sync(wgid);
}

// Stage one 32-row x 64-granule(16B) chunk: thread does rows rp+i*4 (i<8).
__device__ __forceinline__ void stage32(float4* __restrict__ dst,
                                        const char* __restrict__ gbase,
                                        size_t rstrideB, int rp, int kk) {
#pragma unroll
    for (int i = 0; i < 8; ++i) {
        int rs = rp + i * 4;
        cp16(dst + rs * 64 + (kk ^ (rs & 7)),
             gbase + (size_t)rs * rstrideB + kk * 16);
    }
    cp_commit();
}

// 12-output chunk dot: 4 gate + 4 core + 4 tau. ws = weight granule stride.
template <bool SCALE>
__device__ __forceinline__ void dot12(const ulonglong2* __restrict__ sp, int sw,
                                      int kp, int goff,
                                      const ulonglong2* __restrict__ wg,
                                      const ulonglong2* __restrict__ wc,
                                      const ulonglong2* __restrict__ wt,
                                      int ws, unsigned long long sc,
                                      unsigned long long acc[12]) {
#pragma unroll
    for (int j = 0; j < 8; ++j) {
        int l = j * 8 + kp;
        ulonglong2 a = sp[l ^ sw];
        if (SCALE) { a.x = mul2(a.x, sc); a.y = mul2(a.y, sc); }
        int wi = goff + l;
#pragma unroll
        for (int cc = 0; cc < 4; ++cc) {
            ulonglong2 g = wg[cc * ws + wi];
            fma2(acc[cc], a.x, g.x); fma2(acc[cc], a.y, g.y);
            ulonglong2 c = wc[cc * ws + wi];
            fma2(acc[4 + cc], a.x, c.x); fma2(acc[4 + cc], a.y, c.y);
            ulonglong2 t2 = wt[cc * ws + wi];
            fma2(acc[8 + cc], a.x, t2.x); fma2(acc[8 + cc], a.y, t2.y);
        }
    }
}

// Generic 4-col dot (phases C/D), weight col stride 128 granules.
__device__ __forceinline__ void dot4(const ulonglong2* __restrict__ sp, int sw,
                                     int kp, int goff,
                                     const ulonglong2* __restrict__ w,
                                     unsigned long long acc[4][2]) {
#pragma unroll
    for (int j = 0; j < 8; ++j) {
        int l = j * 8 + kp;
        ulonglong2 a = sp[l ^ sw];
        int wi = goff + l;
#pragma unroll
        for (int cc = 0; cc < 4; ++cc) {
            ulonglong2 ww = w[cc * 128 + wi];
            fma2(acc[cc][0], a.x, ww.x);
            fma2(acc[cc][1], a.y, ww.y);
        }
    }
}

__global__ void __launch_bounds__(NTHR, 1)
ctlnn_main(const float* __restrict__ x,
           const float* __restrict__ Wm,  const float* __restrict__ bm,
           const float* __restrict__ Wf1, const float* __restrict__ bf1,
           const float* __restrict__ Wf2, const float* __restrict__ bf2,
           const float* __restrict__ Wt,  const float* __restrict__ bt,
           const float* __restrict__ gamma, const float* __restrict__ beta,
           float* __restrict__ out) {
    extern __shared__ __align__(16) float sm[];
    const int tid = threadIdx.x;
    const int bid = blockIdx.x;
    const int cbase = bid * 4;

    // ---- one-time weight slice load (whole CTA, __syncthreads OK here) ----
    for (int idx = tid; idx < 8 * 256; idx += NTHR) {    // Wm x-rows
        int c = idx >> 8, k = idx & 255;
        int srccol = (c < 4) ? (cbase + c) : (512 + cbase + (c - 4));
        sm[OFF_WMX + idx] = Wm[k * 1024 + srccol];
    }
    for (int idx = tid; idx < 8 * 512; idx += NTHR) {    // Wm h-rows * gamma
        int c = idx >> 9, k = idx & 511;
        int srccol = (c < 4) ? (cbase + c) : (512 + cbase + (c - 4));
        sm[OFF_WMV + idx] = Wm[(256 + k) * 1024 + srccol] * gamma[k];
    }
    for (int idx = tid; idx < 4 * 512; idx += NTHR) {
        int c = idx >> 9, k = idx & 511;
        int col = cbase + c;
        sm[OFF_WF1 + idx] = Wf1[k * 512 + col];
        sm[OFF_WF2 + idx] = Wf2[k * 512 + col];
    }
    if (tid < 4) {
        int col = cbase + tid;
        sm[OFF_B +  0 + tid] = bm[col];
        sm[OFF_B +  4 + tid] = bm[512 + col];
        sm[OFF_B + 12 + tid] = bf1[col];
        sm[OFF_B + 16 + tid] = bf2[col];
        sm[OFF_B + 20 + tid] = gamma[col];
        sm[OFF_B + 24 + tid] = beta[col];
    }
    {   // Bsum/Gsum for the 8 A-columns (gate 0..3, core 4..7)
        int w = tid >> 5, lane = tid & 31;
        if (w < 8) {
            int srccol = (w < 4) ? (cbase + w) : (512 + cbase + (w - 4));
            float sb = 0.f, sg = 0.f;
            for (int k = lane; k < 512; k += 32) {
                float wv = Wm[(256 + k) * 1024 + srccol];
                sb += beta[k] * wv;
                sg += gamma[k] * wv;
            }
#pragma unroll
            for (int o = 16; o; o >>= 1) {
                sb += __shfl_xor_sync(~0u, sb, o);
                sg += __shfl_xor_sync(~0u, sg, o);
            }
            if (lane == 0) { sm[OFF_B + 28 + w] = sb; sm[OFF_B + 36 + w] = sg; }
        }
    }
    __syncthreads();
    // ---- tau fold: WfX = WmX_core@Wt, WfV = WmV_core@Wt (gamma-folded) ----
    {
        float* WtS = sm + OFF_STAGE;            // 4 x 512 [c][j]
        float* Tm  = sm + OFF_STAGE + 2048;     // 24 x 512 tile
        for (int idx = tid; idx < 4 * 512; idx += NTHR) {
            int c = idx >> 9, j = idx & 511;
            WtS[idx] = Wt[j * 512 + cbase + c];
        }
        __syncthreads();
        for (int tile = 0; tile < 32; ++tile) {
            int k0 = tile * 24;
            for (int idx = tid; idx < 24 * 128; idx += NTHR) {
                int row = idx >> 7, jj = idx & 127;
                reinterpret_cast<float4*>(Tm)[row * 128 + jj] =
                    __ldg(reinterpret_cast<const float4*>(
                        Wm + (size_t)(k0 + row) * 1024 + 512) + jj);
            }
            __syncthreads();
            int row = tid >> 2, c = tid & 3;
            if (row < 24) {
                const float4* tm = reinterpret_cast<const float4*>(Tm) + row * 128;
                const float4* wt4 = reinterpret_cast<const float4*>(WtS) + c * 128;
                float s = 0.f;
                for (int jj = 0; jj < 128; ++jj) {
                    float4 a = tm[jj], b = wt4[jj];
                    s += a.x * b.x + a.y * b.y + a.z * b.z + a.w * b.w;
                }
                int k = k0 + row;
                if (k < 256) sm[OFF_WFX + c * 256 + k] = s;
                else         sm[OFF_WFV + c * 512 + (k - 256)] = s;   // raw
            }
            __syncthreads();
        }
        int w = tid >> 5, lane = tid & 31;
        if (w >= 8 && w < 12) {             // BsumT/GsumT for c = w-8
            int c = w - 8;
            float sb = 0.f, sg = 0.f;
            for (int k = lane; k < 512; k += 32) {
                float raw = sm[OFF_WFV + c * 512 + k];
                sb += beta[k] * raw;
                sg += gamma[k] * raw;
            }
#pragma unroll
            for (int o = 16; o; o >>= 1) {
                sb += __shfl_xor_sync(~0u, sb, o);
                sg += __shfl_xor_sync(~0u, sg, o);
            }
            if (lane == 0) { sm[OFF_B + 44 + c] = sb; sm[OFF_B + 48 + c] = sg; }
        } else if (w >= 12) {               // tau const C0 for c = w-12
            int c = w - 12;
            float s = 0.f;
            for (int j = lane; j < 512; j += 32)
                s += bm[512 + j] * WtS[c * 512 + j];
#pragma unroll
            for (int o = 16; o; o >>= 1)
                s += __shfl_xor_sync(~0u, s, o);
            if (lane == 0) sm[OFF_B + 8 + c] = s + bt[cbase + c];
        }
        __syncthreads();
        for (int idx = tid; idx < 4 * 512; idx += NTHR)   // gamma-fold WFV
            sm[OFF_WFV + idx] *= gamma[idx & 511];
        __syncthreads();
    }

    // ---------------- per-warpgroup state ----------------
    const int wgid = tid >> 8;          // 0 or 1: row stream
    const int wtid = tid & 255;
    const int r    = wtid & 31;         // local row
    const int kp   = wtid >> 5;         // K-eighth
    const int sw   = r & 7;
    const int rp   = wtid >> 6;         // staging row phase (0..3)
    const int kk   = wtid & 63;         // staging granule
    const int gR   = wgid * 32 + r;     // global batch row
    const bool owner = (kp == 0);

    float4* bufA = reinterpret_cast<float4*>(sm + OFF_STAGE) + wgid * 4096;
    float4* bufB = bufA + 2048;
    float4* red4 = reinterpret_cast<float4*>(sm + OFF_RED) + wgid * 768;

    const ulonglong2* WMXg = reinterpret_cast<const ulonglong2*>(sm + OFF_WMX);
    const ulonglong2* WMXc = WMXg + 4 * 64;
    const ulonglong2* WFXu = reinterpret_cast<const ulonglong2*>(sm + OFF_WFX);
    const ulonglong2* WMVg = reinterpret_cast<const ulonglong2*>(sm + OFF_WMV);
    const ulonglong2* WMVc = WMVg + 4 * 128;
    const ulonglong2* WFVu = reinterpret_cast<const ulonglong2*>(sm + OFF_WFV);
    const ulonglong2* WF1u = reinterpret_cast<const ulonglong2*>(sm + OFF_WF1);
    const ulonglong2* WF2u = reinterpret_cast<const ulonglong2*>(sm + OFF_WF2);

    const char* xbase = (const char*)(x + (size_t)wgid * 32 * Tt * DIN);
    const char* vbase = (const char*)(g_v  + (size_t)wgid * 32 * Hh);
    const char* zbase = (const char*)(g_z  + (size_t)wgid * 32 * Hh);
    const char* abase = (const char*)(g_a1 + (size_t)wgid * 32 * Hh);

    float hprev[4] = {0.f, 0.f, 0.f, 0.f};
    float dtT[4]   = {0.f, 0.f, 0.f, 0.f};
    float vkeep[4] = {0.f, 0.f, 0.f, 0.f};
    unsigned bar_t = 0;

    // prefetch x(t=0) into bufA
    stage32(bufA, xbase, (size_t)Tt * DIN * 4, rp, kk);

    for (int t = 0; t < Tt; ++t) {
        const int par = t & 1;

        // ============ PHASE A (12 outputs; LN + tau folded) ================
        unsigned long long acc[12] = {};
        cp_wait<0>(); wg_sync(wgid);                       // x(t) ready (bufA)
        dot12<false>(reinterpret_cast<const ulonglong2*>(bufA) + r * 64, sw,
                     kp, 0, WMXg, WMXc, WFXu, 64, 0ull, acc);
        bar_wait(wgid, bar_t, wtid, wgid);                 // hidden by x-dot
        stage32(bufB, vbase, Hh * 4, rp, kk);              // v0 -> B
        stage32(bufA, vbase + 1024, Hh * 4, rp, kk);       // v1 -> A
        float muv = 0.f, rstdv = 0.f;
        if (owner) {
            if (t > 0) {   // finalize step t-1
                int pp = (t - 1) & 1;
                float s = __ldcg(&g_rs[pp * 64 + gR]);
                float q = __ldcg(&g_rq[pp * 64 + gR]);
                muv = s * (1.f / 512.f);
                float var = q * (1.f / 512.f) - muv * muv;
                rstdv = rsqrtf(var + EPSc);
                float4 hn;
                hn.x = (vkeep[0] - muv) * rstdv * sm[OFF_B + 20] + sm[OFF_B + 24];
                hn.y = (vkeep[1] - muv) * rstdv * sm[OFF_B + 21] + sm[OFF_B + 25];
                hn.z = (vkeep[2] - muv) * rstdv * sm[OFF_B + 22] + sm[OFF_B + 26];
                hn.w = (vkeep[3] - muv) * rstdv * sm[OFF_B + 23] + sm[OFF_B + 27];
                *reinterpret_cast<float4*>(
                    out + ((size_t)gR * Tt + (t - 1)) * Hh + cbase) = hn;
                hprev[0] = hn.x; hprev[1] = hn.y; hprev[2] = hn.z; hprev[3] = hn.w;
            }
            sm[OFF_RSTD + wgid * 32 + r] = rstdv;          // 0 at t=0
        }
        cp_wait<1>(); wg_sync(wgid);                       // v0 ready
        unsigned long long rstd2;
        {
            float rv = sm[OFF_RSTD + wgid * 32 + r];
            asm("mov.b64 %0, {%1, %1};" : "=l"(rstd2) : "f"(rv));
        }
        dot12<true>(reinterpret_cast<const ulonglong2*>(bufB) + r * 64, sw,
                    kp, 0, WMVg, WMVc, WFVu, 128, rstd2, acc);
        cp_wait<0>(); wg_sync(wgid);                       // v1 ready
        dot12<true>(reinterpret_cast<const ulonglong2*>(bufA) + r * 64, sw,
                    kp, 64, WMVg, WMVc, WFVu, 128, rstd2, acc);
        {
            float4* rA = red4 + wtid * 3;
            rA[0] = make_float4(hsum(acc[0]), hsum(acc[1]), hsum(acc[2]), hsum(acc[3]));
            rA[1] = make_float4(hsum(acc[4]), hsum(acc[5]), hsum(acc[6]), hsum(acc[7]));
            rA[2] = make_float4(hsum(acc[8]), hsum(acc[9]), hsum(acc[10]), hsum(acc[11]));
        }
        wg_sync(wgid);
        if (owner) {
            float G[4] = {0, 0, 0, 0}, C[4] = {0, 0, 0, 0}, T[4] = {0, 0, 0, 0};
#pragma unroll
            for (int kpp = 0; kpp < 8; ++kpp) {
                const float4* p = red4 + (kpp * 32 + r) * 3;
                float4 a = p[0], b = p[1], d = p[2];
                G[0] += a.x; G[1] += a.y; G[2] += a.z; G[3] += a.w;
                C[0] += b.x; C[1] += b.y; C[2] += b.z; C[3] += b.w;
                T[0] += d.x; T[1] += d.y; T[2] += d.z; T[3] += d.w;
            }
            float mr = muv * rstdv;
            float4 zf;
            float* zp = &zf.x;
#pragma unroll
            for (int cc = 0; cc < 4; ++cc) {
                float gv = G[cc] + sm[OFF_B + cc];
                float cv = C[cc] + sm[OFF_B + 4 + cc];
                float tl = T[cc] + sm[OFF_B + 8 + cc];
                if (t > 0) {
                    gv += sm[OFF_B + 28 + cc]     - mr * sm[OFF_B + 36 + cc];
                    cv += sm[OFF_B + 28 + 4 + cc] - mr * sm[OFF_B + 36 + 4 + cc];
                    tl += sm[OFF_B + 44 + cc]     - mr * sm[OFF_B + 48 + cc];
                }
                float sg = 1.f / (1.f + expf(-gv));
                zp[cc] = sg * tanhf(cv);
                float spv = (tl > 20.f) ? tl : log1pf(expf(tl));
                dtT[cc] = DTc / (spv + 1e-6f);
            }
            *reinterpret_cast<float4*>(&g_z[gR * Hh + cbase]) = zf;
        }
        bar_t += 8;
        bar_arrive(wgid, wtid, wgid);
        bar_wait(wgid, bar_t, wtid, wgid);
        if (bid == 0 && wtid >= 32 && wtid < 96) {   // zero LN accs par^1
            int i = wtid - 32;
            if (i < 32) g_rs[(par ^ 1) * 64 + wgid * 32 + i] = 0.f;
            else        g_rq[(par ^ 1) * 64 + wgid * 32 + (i - 32)] = 0.f;
        }

        // ============ PHASE C: a1 = silu(z@Wf1 + bf1) ======================
        stage32(bufA, zbase,        Hh * 4, rp, kk);
        stage32(bufB, zbase + 1024, Hh * 4, rp, kk);
        unsigned long long af[4][2] = {};
        cp_wait<1>(); wg_sync(wgid);                       // z0 ready
        dot4(reinterpret_cast<const ulonglong2*>(bufA) + r * 64, sw, kp, 0,
             WF1u, af);
        cp_wait<0>(); wg_sync(wgid);                       // z1 ready
        dot4(reinterpret_cast<const ulonglong2*>(bufB) + r * 64, sw, kp, 64,
             WF1u, af);
        red4[wtid] = make_float4(hsum(af[0][0]) + hsum(af[0][1]),
                                 hsum(af[1][0]) + hsum(af[1][1]),
                                 hsum(af[2][0]) + hsum(af[2][1]),
                                 hsum(af[3][0]) + hsum(af[3][1]));
        wg_sync(wgid);
        if (owner) {
            float F[4] = {0, 0, 0, 0};
#pragma unroll
            for (int kpp = 0; kpp < 8; ++kpp) {
                float4 p = red4[kpp * 32 + r];
                F[0] += p.x; F[1] += p.y; F[2] += p.z; F[3] += p.w;
            }
            float4 a1v;
            float* ap = &a1v.x;
#pragma unroll
            for (int cc = 0; cc < 4; ++cc) {
                float f1 = F[cc] + sm[OFF_B + 12 + cc];
                ap[cc] = f1 / (1.f + expf(-f1));
            }
            *reinterpret_cast<float4*>(&g_a1[gR * Hh + cbase]) = a1v;
        }
        bar_t += 8;
        bar_arrive(wgid, wtid, wgid);
        bar_wait(wgid, bar_t, wtid, wgid);

        // ===== PHASE D: f = a1@Wf2 + bf2; v = h + dt/tau * f ===============
        stage32(bufA, abase,        Hh * 4, rp, kk);
        stage32(bufB, abase + 1024, Hh * 4, rp, kk);
        unsigned long long ao[4][2] = {};
        cp_wait<1>(); wg_sync(wgid);                       // a1_0 ready
        dot4(reinterpret_cast<const ulonglong2*>(bufA) + r * 64, sw, kp, 0,
             WF2u, ao);
        wg_sync(wgid);
        if (t + 1 < Tt) {                                  // x(t+1) -> A
            stage32(bufA, xbase + (size_t)(t + 1) * DIN * 4,
                    (size_t)Tt * DIN * 4, rp, kk);
            cp_wait<1>();
        } else {
            cp_wait<0>();
        }
        wg_sync(wgid);                                     // a1_1 ready
        dot4(reinterpret_cast<const ulonglong2*>(bufB) + r * 64, sw, kp, 64,
             WF2u, ao);
        red4[wtid] = make_float4(hsum(ao[0][0]) + hsum(ao[0][1]),
                                 hsum(ao[1][0]) + hsum(ao[1][1]),
                                 hsum(ao[2][0]) + hsum(ao[2][1]),
                                 hsum(ao[3][0]) + hsum(ao[3][1]));
        wg_sync(wgid);
        if (owner) {
            float F[4] = {0, 0, 0, 0};
#pragma unroll
            for (int kpp = 0; kpp < 8; ++kpp) {
                float4 p = red4[kpp * 32 + r];
                F[0] += p.x; F[1] += p.y; F[2] += p.z; F[3] += p.w;
            }
            float ssum = 0.f, qsum = 0.f;
            float4 vv;
            float* vp = &vv.x;
#pragma unroll
            for (int cc = 0; cc < 4; ++cc) {
                float f = F[cc] + sm[OFF_B + 16 + cc];
                float v = hprev[cc] + dtT[cc] * f;
                vkeep[cc] = v;
                vp[cc] = v;
                ssum += v; qsum += v * v;
            }
            *reinterpret_cast<float4*>(&g_v[gR * Hh + cbase]) = vv;
            atomicAdd(&g_rs[par * 64 + gR], ssum);
            atomicAdd(&g_rq[par * 64 + gR], qsum);
        }
        bar_arrive(wgid, wtid, wgid);     // split: wait in next phase A
        bar_t += 8;
    }

    bar_wait(wgid, bar_t, wtid, wgid);
    // final output row (t = Tt-1)
    if (owner) {
        int pp = (Tt - 1) & 1;
        float s = __ldcg(&g_rs[pp * 64 + gR]);
        float q = __ldcg(&g_rq[pp * 64 + gR]);
        float muv = s * (1.f / 512.f);
        float var = q * (1.f / 512.f) - muv * muv;
        float rstdv = rsqrtf(var + EPSc);
        float4 hn;
        hn.x = (vkeep[0] - muv) * rstdv * sm[OFF_B + 20] + sm[OFF_B + 24];
        hn.y = (vkeep[1] - muv) * rstdv * sm[OFF_B + 21] + sm[OFF_B + 25];
        hn.z = (vkeep[2] - muv) * rstdv * sm[OFF_B + 22] + sm[OFF_B + 26];
        hn.w = (vkeep[3] - muv) * rstdv * sm[OFF_B + 23] + sm[OFF_B + 27];
        *reinterpret_cast<float4*>(
            out + ((size_t)gR * Tt + (Tt - 1)) * Hh + cbase) = hn;
    }
}

extern "C" void kernel_launch(void* const* d_in, const int* in_sizes, int n_in,
                              void* d_out, int out_size) {
    const float* x     = (const float*)d_in[0];
    const float* Wm    = (const float*)d_in[1];
    const float* bm    = (const float*)d_in[2];
    const float* Wf1   = (const float*)d_in[3];
    const float* bf1   = (const float*)d_in[4];
    const float* Wf2   = (const float*)d_in[5];
    const float* bf2   = (const float*)d_in[6];
    const float* Wt    = (const float*)d_in[7];
    const float* bt    = (const float*)d_in[8];
    const float* gamma = (const float*)d_in[9];
    const float* beta  = (const float*)d_in[10];
    float* out = (float*)d_out;

    cudaFuncSetAttribute(ctlnn_main, cudaFuncAttributeMaxDynamicSharedMemorySize,
                         SMEM_FLOATS * sizeof(float));

    ctlnn_reset<<<64, 256>>>();
    ctlnn_main<<<NCTA, NTHR, SMEM_FLOATS * sizeof(float)>>>(
        x, Wm, bm, Wf1, bf1, Wf2, bf2, Wt, bt, gamma, beta, out);
}

// round 12
// speedup vs baseline: 1.1058x; 1.1058x over previous
#include <cuda_runtime.h>
#include <cmath>

// ---------------------------------------------------------------------------
// CTLNN persistent kernel, round 12: warp-specialized dual row-streams WITH
// an enforced one-phase offset between streams.
// 128 CTAs; each owns 4 H-columns. wg0 (threads 0-255) processes batch rows
// 0-31, wg1 rows 32-63; each wg has its own stage buffers, distributed
// grid-barrier set, and bar.sync-scoped syncs. wg1 delays loop entry until
// stream 0 completes phase A of t=0 chip-wide, so the streams stay offset:
// one stream computes while the other sits in barrier/L2-staging stalls.
// tau folded through the mapper (3 phases/step); LayerNorm folded into
// phase A; cp.async double-buffered staging; FFMA2 inner loops.
// ---------------------------------------------------------------------------

namespace {
constexpr int Tt   = 1024;
constexpr int DIN  = 256;
constexpr int Hh   = 512;
constexpr int NCTA = 128;
constexpr int NTHR = 512;
constexpr int NBAR = 16;
constexpr int BARSTRIDE = 32;
constexpr float DTc  = 0.01f;
constexpr float EPSc = 1e-5f;

// SMEM float offsets
constexpr int OFF_WMX   = 0;        // 8 x 256 (x-rows: 4 gate + 4 core cols)
constexpr int OFF_WMV   = 2048;     // 8 x 512 (h-rows, gamma-folded)
constexpr int OFF_WFX   = 6144;     // 4 x 256 tau x-fold
constexpr int OFF_WFV   = 7168;     // 4 x 512 tau v-fold (gamma-folded)
constexpr int OFF_WF1   = 9216;     // 4 x 512
constexpr int OFF_WF2   = 11264;    // 4 x 512
constexpr int OFF_STAGE = 13312;    // 4 buffers x 2048 float4 (32KB each)
constexpr int OFF_RED   = 46080;    // 2 wg x 768 float4
constexpr int OFF_B     = 52224;    // 64 consts
constexpr int OFF_RSTD  = 52288;    // 2 x 32
constexpr int SMEM_FLOATS = 52352;  // ~209.4 KB
// OFF_B: 0 bmg[4] 4 bmc[4] 8 tauC0[4] 12 bf1[4] 16 bf2[4] 20 gam[4] 24 bet[4]
//        28 Bsum[8] (g,core) 36 Gsum[8] 44 BsumT[4] 48 GsumT[4]
}

// Cross-CTA state
__device__ unsigned g_barArr[2][NBAR * BARSTRIDE];   // one set per row-stream
__device__ float g_rs[128], g_rq[128];               // [par][globalRow]
__device__ float g_v[64 * Hh];
__device__ float g_z[64 * Hh];
__device__ float g_a1[64 * Hh];

__global__ void ctlnn_reset() {
    int i = blockIdx.x * blockDim.x + threadIdx.x;
    if (i < 2 * NBAR * BARSTRIDE) (&g_barArr[0][0])[i] = 0u;
    if (i < 128) { g_rs[i] = 0.f; g_rq[i] = 0.f; }
    for (int k = i; k < 64 * Hh; k += gridDim.x * blockDim.x) g_v[k] = 0.f;
}

// ---- helpers --------------------------------------------------------------
__device__ __forceinline__ void cp16(float4* dst, const void* src) {
    unsigned s = (unsigned)__cvta_generic_to_shared(dst);
    asm volatile("cp.async.cg.shared.global [%0], [%1], 16;" :: "r"(s), "l"(src));
}
__device__ __forceinline__ void cp_commit() {
    asm volatile("cp.async.commit_group;" ::: "memory");
}
template <int N>
__device__ __forceinline__ void cp_wait() {
    asm volatile("cp.async.wait_group %0;" :: "n"(N) : "memory");
}
__device__ __forceinline__ void fma2(unsigned long long& d,
                                     unsigned long long a, unsigned long long b) {
    asm volatile("fma.rn.f32x2 %0, %1, %2, %3;" : "=l"(d) : "l"(a), "l"(b), "l"(d));
}
__device__ __forceinline__ unsigned long long mul2(unsigned long long a,
                                                   unsigned long long b) {
    unsigned long long d;
    asm("mul.rn.f32x2 %0, %1, %2;" : "=l"(d) : "l"(a), "l"(b));
    return d;
}
__device__ __forceinline__ float hsum(unsigned long long u) {
    float lo, hi;
    asm("mov.b64 {%0,%1}, %2;" : "=f"(lo), "=f"(hi) : "l"(u));
    return lo + hi;
}
// per-warpgroup sync (named barrier, 256 threads)
__device__ __forceinline__ void wg_sync(int wgid) {
    asm volatile("bar.sync %0, 256;" :: "r"(1 + wgid) : "memory");
}

// Distributed per-stream barrier.
__device__ __forceinline__ void bar_arrive(int s, int wtid, int wgid) {
    __threadfence();
    wg_sync(wgid);
    if (wtid == 0)
        atomicAdd(&g_barArr[s][(blockIdx.x & (NBAR - 1)) * BARSTRIDE], 1u);
}
__device__ __forceinline__ void bar_wait(int s, unsigned target8, int wtid,
                                         int wgid) {
    if (wtid < NBAR) {
        unsigned v;
        do {
            asm volatile("ld.global.acquire.gpu.u32 %0, [%1];"
                         : "=r"(v) : "l"(&g_barArr[s][wtid * BARSTRIDE]));
        } while (v < target8);
    }
    wg_sync(wgid);
}

// Stage one 32-row x 64-granule(16B) chunk: thread does rows rp+i*4 (i<8).
__device__ __forceinline__ void stage32(float4* __restrict__ dst,
                                        const char* __restrict__ gbase,
                                        size_t rstrideB, int rp, int kk) {
#pragma unroll
    for (int i = 0; i < 8; ++i) {
        int rs = rp + i * 4;
        cp16(dst + rs * 64 + (kk ^ (rs & 7)),
             gbase + (size_t)rs * rstrideB + kk * 16);
    }
    cp_commit();
}

// 12-output chunk dot: 4 gate + 4 core + 4 tau. ws = weight granule stride.
template <bool SCALE>
__device__ __forceinline__ void dot12(const ulonglong2* __restrict__ sp, int sw,
                                      int kp, int goff,
                                      const ulonglong2* __restrict__ wg,
                                      const ulonglong2* __restrict__ wc,
                                      const ulonglong2* __restrict__ wt,
                                      int ws, unsigned long long sc,
                                      unsigned long long acc[12]) {
#pragma unroll
    for (int j = 0; j < 8; ++j) {
        int l = j * 8 + kp;
        ulonglong2 a = sp[l ^ sw];
        if (SCALE) { a.x = mul2(a.x, sc); a.y = mul2(a.y, sc); }
        int wi = goff + l;
#pragma unroll
        for (int cc = 0; cc < 4; ++cc) {
            ulonglong2 g = wg[cc * ws + wi];
            fma2(acc[cc], a.x, g.x); fma2(acc[cc], a.y, g.y);
            ulonglong2 c = wc[cc * ws + wi];
            fma2(acc[4 + cc], a.x, c.x); fma2(acc[4 + cc], a.y, c.y);
            ulonglong2 t2 = wt[cc * ws + wi];
            fma2(acc[8 + cc], a.x, t2.x); fma2(acc[8 + cc], a.y, t2.y);
        }
    }
}

// Generic 4-col dot (phases C/D), weight col stride 128 granules.
__device__ __forceinline__ void dot4(const ulonglong2* __restrict__ sp, int sw,
                                     int kp, int goff,
                                     const ulonglong2* __restrict__ w,
                                     unsigned long long acc[4][2]) {
#pragma unroll
    for (int j = 0; j < 8; ++j) {
        int l = j * 8 + kp;
        ulonglong2 a = sp[l ^ sw];
        int wi = goff + l;
#pragma unroll
        for (int cc = 0; cc < 4; ++cc) {
            ulonglong2 ww = w[cc * 128 + wi];
            fma2(acc[cc][0], a.x, ww.x);
            fma2(acc[cc][1], a.y, ww.y);
        }
    }
}

__global__ void __launch_bounds__(NTHR, 1)
ctlnn_main(const float* __restrict__ x,
           const float* __restrict__ Wm,  const float* __restrict__ bm,
           const float* __restrict__ Wf1, const float* __restrict__ bf1,
           const float* __restrict__ Wf2, const float* __restrict__ bf2,
           const float* __restrict__ Wt,  const float* __restrict__ bt,
           const float* __restrict__ gamma, const float* __restrict__ beta,
           float* __restrict__ out) {
    extern __shared__ __align__(16) float sm[];
    const int tid = threadIdx.x;
    const int bid = blockIdx.x;
    const int cbase = bid * 4;

    // ---- one-time weight slice load (whole CTA, __syncthreads OK here) ----
    for (int idx = tid; idx < 8 * 256; idx += NTHR) {    // Wm x-rows
        int c = idx >> 8, k = idx & 255;
        int srccol = (c < 4) ? (cbase + c) : (512 + cbase + (c - 4));
        sm[OFF_WMX + idx] = Wm[k * 1024 + srccol];
    }
    for (int idx = tid; idx < 8 * 512; idx += NTHR) {    // Wm h-rows * gamma
        int c = idx >> 9, k = idx & 511;
        int srccol = (c < 4) ? (cbase + c) : (512 + cbase + (c - 4));
        sm[OFF_WMV + idx] = Wm[(256 + k) * 1024 + srccol] * gamma[k];
    }
    for (int idx = tid; idx < 4 * 512; idx += NTHR) {
        int c = idx >> 9, k = idx & 511;
        int col = cbase + c;
        sm[OFF_WF1 + idx] = Wf1[k * 512 + col];
        sm[OFF_WF2 + idx] = Wf2[k * 512 + col];
    }
    if (tid < 4) {
        int col = cbase + tid;
        sm[OFF_B +  0 + tid] = bm[col];
        sm[OFF_B +  4 + tid] = bm[512 + col];
        sm[OFF_B + 12 + tid] = bf1[col];
        sm[OFF_B + 16 + tid] = bf2[col];
        sm[OFF_B + 20 + tid] = gamma[col];
        sm[OFF_B + 24 + tid] = beta[col];
    }
    {   // Bsum/Gsum for the 8 A-columns (gate 0..3, core 4..7)
        int w = tid >> 5, lane = tid & 31;
        if (w < 8) {
            int srccol = (w < 4) ? (cbase + w) : (512 + cbase + (w - 4));
            float sb = 0.f, sg = 0.f;
            for (int k = lane; k < 512; k += 32) {
                float wv = Wm[(256 + k) * 1024 + srccol];
                sb += beta[k] * wv;
                sg += gamma[k] * wv;
            }
#pragma unroll
            for (int o = 16; o; o >>= 1) {
                sb += __shfl_xor_sync(~0u, sb, o);
                sg += __shfl_xor_sync(~0u, sg, o);
            }
            if (lane == 0) { sm[OFF_B + 28 + w] = sb; sm[OFF_B + 36 + w] = sg; }
        }
    }
    __syncthreads();
    // ---- tau fold: WfX = WmX_core@Wt, WfV = WmV_core@Wt (gamma-folded) ----
    {
        float* WtS = sm + OFF_STAGE;            // 4 x 512 [c][j]
        float* Tm  = sm + OFF_STAGE + 2048;     // 24 x 512 tile
        for (int idx = tid; idx < 4 * 512; idx += NTHR) {
            int c = idx >> 9, j = idx & 511;
            WtS[idx] = Wt[j * 512 + cbase + c];
        }
        __syncthreads();
        for (int tile = 0; tile < 32; ++tile) {
            int k0 = tile * 24;
            for (int idx = tid; idx < 24 * 128; idx += NTHR) {
                int row = idx >> 7, jj = idx & 127;
                reinterpret_cast<float4*>(Tm)[row * 128 + jj] =
                    __ldg(reinterpret_cast<const float4*>(
                        Wm + (size_t)(k0 + row) * 1024 + 512) + jj);
            }
            __syncthreads();
            int row = tid >> 2, c = tid & 3;
            if (row < 24) {
                const float4* tm = reinterpret_cast<const float4*>(Tm) + row * 128;
                const float4* wt4 = reinterpret_cast<const float4*>(WtS) + c * 128;
                float s = 0.f;
                for (int jj = 0; jj < 128; ++jj) {
                    float4 a = tm[jj], b = wt4[jj];
                    s += a.x * b.x + a.y * b.y + a.z * b.z + a.w * b.w;
                }
                int k = k0 + row;
                if (k < 256) sm[OFF_WFX + c * 256 + k] = s;
                else         sm[OFF_WFV + c * 512 + (k - 256)] = s;   // raw
            }
            __syncthreads();
        }
        int w = tid >> 5, lane = tid & 31;
        if (w >= 8 && w < 12) {             // BsumT/GsumT for c = w-8
            int c = w - 8;
            float sb = 0.f, sg = 0.f;
            for (int k = lane; k < 512; k += 32) {
                float raw = sm[OFF_WFV + c * 512 + k];
                sb += beta[k] * raw;
                sg += gamma[k] * raw;
            }
#pragma unroll
            for (int o = 16; o; o >>= 1) {
                sb += __shfl_xor_sync(~0u, sb, o);
                sg += __shfl_xor_sync(~0u, sg, o);
            }
            if (lane == 0) { sm[OFF_B + 44 + c] = sb; sm[OFF_B + 48 + c] = sg; }
        } else if (w >= 12) {               // tau const C0 for c = w-12
            int c = w - 12;
            float s = 0.f;
            for (int j = lane; j < 512; j += 32)
                s += bm[512 + j] * WtS[c * 512 + j];
#pragma unroll
            for (int o = 16; o; o >>= 1)
                s += __shfl_xor_sync(~0u, s, o);
            if (lane == 0) sm[OFF_B + 8 + c] = s + bt[cbase + c];
        }
        __syncthreads();
        for (int idx = tid; idx < 4 * 512; idx += NTHR)   // gamma-fold WFV
            sm[OFF_WFV + idx] *= gamma[idx & 511];
        __syncthreads();
    }

    // ---------------- per-warpgroup state ----------------
    const int wgid = tid >> 8;          // 0 or 1: row stream
    const int wtid = tid & 255;
    const int r    = wtid & 31;         // local row
    const int kp   = wtid >> 5;         // K-eighth
    const int sw   = r & 7;
    const int rp   = wtid >> 6;         // staging row phase (0..3)
    const int kk   = wtid & 63;         // staging granule
    const int gR   = wgid * 32 + r;     // global batch row
    const bool owner = (kp == 0);

    float4* bufA = reinterpret_cast<float4*>(sm + OFF_STAGE) + wgid * 4096;
    float4* bufB = bufA + 2048;
    float4* red4 = reinterpret_cast<float4*>(sm + OFF_RED) + wgid * 768;

    const ulonglong2* WMXg = reinterpret_cast<const ulonglong2*>(sm + OFF_WMX);
    const ulonglong2* WMXc = WMXg + 4 * 64;
    const ulonglong2* WFXu = reinterpret_cast<const ulonglong2*>(sm + OFF_WFX);
    const ulonglong2* WMVg = reinterpret_cast<const ulonglong2*>(sm + OFF_WMV);
    const ulonglong2* WMVc = WMVg + 4 * 128;
    const ulonglong2* WFVu = reinterpret_cast<const ulonglong2*>(sm + OFF_WFV);
    const ulonglong2* WF1u = reinterpret_cast<const ulonglong2*>(sm + OFF_WF1);
    const ulonglong2* WF2u = reinterpret_cast<const ulonglong2*>(sm + OFF_WF2);

    const char* xbase = (const char*)(x + (size_t)wgid * 32 * Tt * DIN);
    const char* vbase = (const char*)(g_v  + (size_t)wgid * 32 * Hh);
    const char* zbase = (const char*)(g_z  + (size_t)wgid * 32 * Hh);
    const char* abase = (const char*)(g_a1 + (size_t)wgid * 32 * Hh);

    float hprev[4] = {0.f, 0.f, 0.f, 0.f};
    float dtT[4]   = {0.f, 0.f, 0.f, 0.f};
    float vkeep[4] = {0.f, 0.f, 0.f, 0.f};
    unsigned bar_t = 0;

    // prefetch x(t=0) into bufA
    stage32(bufA, xbase, (size_t)Tt * DIN * 4, rp, kk);

    // ---- ENFORCED STREAM OFFSET: wg1 starts one phase behind wg0 ----------
    // wg1 waits until stream 0 has completed phase A of t=0 chip-wide
    // (stream-0 counters reach 8). wg0 never waits on wg1 => no deadlock.
    if (wgid == 1) {
        if (wtid < NBAR) {
            unsigned v;
            do {
                asm volatile("ld.global.acquire.gpu.u32 %0, [%1];"
                             : "=r"(v) : "l"(&g_barArr[0][wtid * BARSTRIDE]));
            } while (v < 8);
        }
        wg_sync(1);
    }

    for (int t = 0; t < Tt; ++t) {
        const int par = t & 1;

        // ============ PHASE A (12 outputs; LN + tau folded) ================
        unsigned long long acc[12] = {};
        cp_wait<0>(); wg_sync(wgid);                       // x(t) ready (bufA)
        dot12<false>(reinterpret_cast<const ulonglong2*>(bufA) + r * 64, sw,
                     kp, 0, WMXg, WMXc, WFXu, 64, 0ull, acc);
        bar_wait(wgid, bar_t, wtid, wgid);                 // hidden by x-dot
        stage32(bufB, vbase, Hh * 4, rp, kk);              // v0 -> B
        stage32(bufA, vbase + 1024, Hh * 4, rp, kk);       // v1 -> A
        float muv = 0.f, rstdv = 0.f;
        if (owner) {
            if (t > 0) {   // finalize step t-1
                int pp = (t - 1) & 1;
                float s = __ldcg(&g_rs[pp * 64 + gR]);
                float q = __ldcg(&g_rq[pp * 64 + gR]);
                muv = s * (1.f / 512.f);
                float var = q * (1.f / 512.f) - muv * muv;
                rstdv = rsqrtf(var + EPSc);
                float4 hn;
                hn.x = (vkeep[0] - muv) * rstdv * sm[OFF_B + 20] + sm[OFF_B + 24];
                hn.y = (vkeep[1] - muv) * rstdv * sm[OFF_B + 21] + sm[OFF_B + 25];
                hn.z = (vkeep[2] - muv) * rstdv * sm[OFF_B + 22] + sm[OFF_B + 26];
                hn.w = (vkeep[3] - muv) * rstdv * sm[OFF_B + 23] + sm[OFF_B + 27];
                *reinterpret_cast<float4*>(
                    out + ((size_t)gR * Tt + (t - 1)) * Hh + cbase) = hn;
                hprev[0] = hn.x; hprev[1] = hn.y; hprev[2] = hn.z; hprev[3] = hn.w;
            }
            sm[OFF_RSTD + wgid * 32 + r] = rstdv;          // 0 at t=0
        }
        cp_wait<1>(); wg_sync(wgid);                       // v0 ready
        unsigned long long rstd2;
        {
            float rv = sm[OFF_RSTD + wgid * 32 + r];
            asm("mov.b64 %0, {%1, %1};" : "=l"(rstd2) : "f"(rv));
        }
        dot12<true>(reinterpret_cast<const ulonglong2*>(bufB) + r * 64, sw,
                    kp, 0, WMVg, WMVc, WFVu, 128, rstd2, acc);
        cp_wait<0>(); wg_sync(wgid);                       // v1 ready
        dot12<true>(reinterpret_cast<const ulonglong2*>(bufA) + r * 64, sw,
                    kp, 64, WMVg, WMVc, WFVu, 128, rstd2, acc);
        {
            float4* rA = red4 + wtid * 3;
            rA[0] = make_float4(hsum(acc[0]), hsum(acc[1]), hsum(acc[2]), hsum(acc[3]));
            rA[1] = make_float4(hsum(acc[4]), hsum(acc[5]), hsum(acc[6]), hsum(acc[7]));
            rA[2] = make_float4(hsum(acc[8]), hsum(acc[9]), hsum(acc[10]), hsum(acc[11]));
        }
        wg_sync(wgid);
        if (owner) {
            float G[4] = {0, 0, 0, 0}, C[4] = {0, 0, 0, 0}, T[4] = {0, 0, 0, 0};
#pragma unroll
            for (int kpp = 0; kpp < 8; ++kpp) {
                const float4* p = red4 + (kpp * 32 + r) * 3;
                float4 a = p[0], b = p[1], d = p[2];
                G[0] += a.x; G[1] += a.y; G[2] += a.z; G[3] += a.w;
                C[0] += b.x; C[1] += b.y; C[2] += b.z; C[3] += b.w;
                T[0] += d.x; T[1] += d.y; T[2] += d.z; T[3] += d.w;
            }
            float mr = muv * rstdv;
            float4 zf;
            float* zp = &zf.x;
#pragma unroll
            for (int cc = 0; cc < 4; ++cc) {
                float gv = G[cc] + sm[OFF_B + cc];
                float cv = C[cc] + sm[OFF_B + 4 + cc];
                float tl = T[cc] + sm[OFF_B + 8 + cc];
                if (t > 0) {
                    gv += sm[OFF_B + 28 + cc]     - mr * sm[OFF_B + 36 + cc];
                    cv += sm[OFF_B + 28 + 4 + cc] - mr * sm[OFF_B + 36 + 4 + cc];
                    tl += sm[OFF_B + 44 + cc]     - mr * sm[OFF_B + 48 + cc];
                }
                float sg = 1.f / (1.f + expf(-gv));
                zp[cc] = sg * tanhf(cv);
                float spv = (tl > 20.f) ? tl : log1pf(expf(tl));
                dtT[cc] = DTc / (spv + 1e-6f);
            }
            *reinterpret_cast<float4*>(&g_z[gR * Hh + cbase]) = zf;
        }
        bar_t += 8;
        bar_arrive(wgid, wtid, wgid);
        bar_wait(wgid, bar_t, wtid, wgid);
        if (bid == 0 && wtid >= 32 && wtid < 96) {   // zero LN accs par^1
            int i = wtid - 32;
            if (i < 32) g_rs[(par ^ 1) * 64 + wgid * 32 + i] = 0.f;
            else        g_rq[(par ^ 1) * 64 + wgid * 32 + (i - 32)] = 0.f;
        }

        // ============ PHASE C: a1 = silu(z@Wf1 + bf1) ======================
        stage32(bufA, zbase,        Hh * 4, rp, kk);
        stage32(bufB, zbase + 1024, Hh * 4, rp, kk);
        unsigned long long af[4][2] = {};
        cp_wait<1>(); wg_sync(wgid);                       // z0 ready
        dot4(reinterpret_cast<const ulonglong2*>(bufA) + r * 64, sw, kp, 0,
             WF1u, af);
        cp_wait<0>(); wg_sync(wgid);                       // z1 ready
        dot4(reinterpret_cast<const ulonglong2*>(bufB) + r * 64, sw, kp, 64,
             WF1u, af);
        red4[wtid] = make_float4(hsum(af[0][0]) + hsum(af[0][1]),
                                 hsum(af[1][0]) + hsum(af[1][1]),
                                 hsum(af[2][0]) + hsum(af[2][1]),
                                 hsum(af[3][0]) + hsum(af[3][1]));
        wg_sync(wgid);
        if (owner) {
            float F[4] = {0, 0, 0, 0};
#pragma unroll
            for (int kpp = 0; kpp < 8; ++kpp) {
                float4 p = red4[kpp * 32 + r];
                F[0] += p.x; F[1] += p.y; F[2] += p.z; F[3] += p.w;
            }
            float4 a1v;
            float* ap = &a1v.x;
#pragma unroll
            for (int cc = 0; cc < 4; ++cc) {
                float f1 = F[cc] + sm[OFF_B + 12 + cc];
                ap[cc] = f1 / (1.f + expf(-f1));
            }
            *reinterpret_cast<float4*>(&g_a1[gR * Hh + cbase]) = a1v;
        }
        bar_t += 8;
        bar_arrive(wgid, wtid, wgid);
        bar_wait(wgid, bar_t, wtid, wgid);

        // ===== PHASE D: f = a1@Wf2 + bf2; v = h + dt/tau * f ===============
        stage32(bufA, abase,        Hh * 4, rp, kk);
        stage32(bufB, abase + 1024, Hh * 4, rp, kk);
        unsigned long long ao[4][2] = {};
        cp_wait<1>(); wg_sync(wgid);                       // a1_0 ready
        dot4(reinterpret_cast<const ulonglong2*>(bufA) + r * 64, sw, kp, 0,
             WF2u, ao);
        wg_sync(wgid);
        if (t + 1 < Tt) {                                  // x(t+1) -> A
            stage32(bufA, xbase + (size_t)(t + 1) * DIN * 4,
                    (size_t)Tt * DIN * 4, rp, kk);
            cp_wait<1>();
        } else {
            cp_wait<0>();
        }
        wg_sync(wgid);                                     // a1_1 ready
        dot4(reinterpret_cast<const ulonglong2*>(bufB) + r * 64, sw, kp, 64,
             WF2u, ao);
        red4[wtid] = make_float4(hsum(ao[0][0]) + hsum(ao[0][1]),
                                 hsum(ao[1][0]) + hsum(ao[1][1]),
                                 hsum(ao[2][0]) + hsum(ao[2][1]),
                                 hsum(ao[3][0]) + hsum(ao[3][1]));
        wg_sync(wgid);
        if (owner) {
            float F[4] = {0, 0, 0, 0};
#pragma unroll
            for (int kpp = 0; kpp < 8; ++kpp) {
                float4 p = red4[kpp * 32 + r];
                F[0] += p.x; F[1] += p.y; F[2] += p.z; F[3] += p.w;
            }
            float ssum = 0.f, qsum = 0.f;
            float4 vv;
            float* vp = &vv.x;
#pragma unroll
            for (int cc = 0; cc < 4; ++cc) {
                float f = F[cc] + sm[OFF_B + 16 + cc];
                float v = hprev[cc] + dtT[cc] * f;
                vkeep[cc] = v;
                vp[cc] = v;
                ssum += v; qsum += v * v;
            }
            *reinterpret_cast<float4*>(&g_v[gR * Hh + cbase]) = vv;
            atomicAdd(&g_rs[par * 64 + gR], ssum);
            atomicAdd(&g_rq[par * 64 + gR], qsum);
        }
        bar_arrive(wgid, wtid, wgid);     // split: wait in next phase A
        bar_t += 8;
    }

    bar_wait(wgid, bar_t, wtid, wgid);
    // final output row (t = Tt-1)
    if (owner) {
        int pp = (Tt - 1) & 1;
        float s = __ldcg(&g_rs[pp * 64 + gR]);
        float q = __ldcg(&g_rq[pp * 64 + gR]);
        float muv = s * (1.f / 512.f);
        float var = q * (1.f / 512.f) - muv * muv;
        float rstdv = rsqrtf(var + EPSc);
        float4 hn;
        hn.x = (vkeep[0] - muv) * rstdv * sm[OFF_B + 20] + sm[OFF_B + 24];
        hn.y = (vkeep[1] - muv) * rstdv * sm[OFF_B + 21] + sm[OFF_B + 25];
        hn.z = (vkeep[2] - muv) * rstdv * sm[OFF_B + 22] + sm[OFF_B + 26];
        hn.w = (vkeep[3] - muv) * rstdv * sm[OFF_B + 23] + sm[OFF_B + 27];
        *reinterpret_cast<float4*>(
            out + ((size_t)gR * Tt + (Tt - 1)) * Hh + cbase) = hn;
    }
}

extern "C" void kernel_launch(void* const* d_in, const int* in_sizes, int n_in,
                              void* d_out, int out_size) {
    const float* x     = (const float*)d_in[0];
    const float* Wm    = (const float*)d_in[1];
    const float* bm    = (const float*)d_in[2];
    const float* Wf1   = (const float*)d_in[3];
    const float* bf1   = (const float*)d_in[4];
    const float* Wf2   = (const float*)d_in[5];
    const float* bf2   = (const float*)d_in[6];
    const float* Wt    = (const float*)d_in[7];
    const float* bt    = (const float*)d_in[8];
    const float* gamma = (const float*)d_in[9];
    const float* beta  = (const float*)d_in[10];
    float* out = (float*)d_out;

    cudaFuncSetAttribute(ctlnn_main, cudaFuncAttributeMaxDynamicSharedMemorySize,
                         SMEM_FLOATS * sizeof(float));

    ctlnn_reset<<<64, 256>>>();
    ctlnn_main<<<NCTA, NTHR, SMEM_FLOATS * sizeof(float)>>>(
        x, Wm, bm, Wf1, bf1, Wf2, bf2, Wt, bt, gamma, beta, out);
}

// round 13
// speedup vs baseline: 1.2681x; 1.1467x over previous
#include <cuda_runtime.h>
#include <cmath>

// ---------------------------------------------------------------------------
// CTLNN persistent kernel, round 13: FOUR staggered row-streams.
// 128 CTAs; each owns 4 H-columns. Each CTA splits into 4 streams of 128
// threads (16 batch rows each), cascaded one phase apart; each stream has its
// own stage buffers, distributed grid-barrier set, and bar.sync scope.
// Per stream: thread (r:16, kslot:8) computes all 4 CTA columns over 8
// granules; warps pair 2 kslots (weight reads stay 1 wf/granule-equivalent).
// Epilogues (nonlinearities, LN, publishes) distributed over all 128 threads;
// per-row recurrence state lives in SMEM. tau folded through the mapper
// (3 phases/step); LayerNorm folded into phase A; cp.async double-buffered
// staging; FFMA2 inner loops.
// ---------------------------------------------------------------------------

namespace {
constexpr int Tt   = 1024;
constexpr int DIN  = 256;
constexpr int Hh   = 512;
constexpr int NCTA = 128;
constexpr int NTHR = 512;
constexpr int NBAR = 16;
constexpr int BARSTRIDE = 32;
constexpr float DTc  = 0.01f;
constexpr float EPSc = 1e-5f;

// SMEM float offsets
constexpr int OFF_WMX   = 0;        // 8 x 256 (x-rows: 4 gate + 4 core cols)
constexpr int OFF_WMV   = 2048;     // 8 x 512 (h-rows, gamma-folded)
constexpr int OFF_WFX   = 6144;     // 4 x 256 tau x-fold
constexpr int OFF_WFV   = 7168;     // 4 x 512 tau v-fold (gamma-folded)
constexpr int OFF_WF1   = 9216;     // 4 x 512
constexpr int OFF_WF2   = 11264;    // 4 x 512
constexpr int OFF_STAGE = 13312;    // 4 streams x 2 buffers x 1024 float4
constexpr int OFF_RED   = 46080;    // 4 streams x 128 x 3 float4 = 6144
constexpr int OFF_B     = 52224;    // 64 consts
constexpr int OFF_ST    = 52288;    // 4 streams x 256 state floats
constexpr int SMEM_FLOATS = 53312;  // ~213.2 KB
// OFF_B: 0 bmg[4] 4 bmc[4] 8 tauC0[4] 12 bf1[4] 16 bf2[4] 20 gam[4] 24 bet[4]
//        28 Bsum[8] (g,core) 36 Gsum[8] 44 BsumT[4] 48 GsumT[4]
// per-stream state block (256): 0 rstd[16] 16 mr[16] 32 dtT[64] 96 h[64] 160 v[64]
}

// Cross-CTA state
__device__ unsigned g_barArr[4][NBAR * BARSTRIDE];   // per-stream counters
__device__ float g_rs[128], g_rq[128];               // [par][globalRow]
__device__ float g_v[64 * Hh];
__device__ float g_z[64 * Hh];
__device__ float g_a1[64 * Hh];

__global__ void ctlnn_reset() {
    int i = blockIdx.x * blockDim.x + threadIdx.x;
    if (i < 4 * NBAR * BARSTRIDE) (&g_barArr[0][0])[i] = 0u;
    if (i < 128) { g_rs[i] = 0.f; g_rq[i] = 0.f; }
    for (int k = i; k < 64 * Hh; k += gridDim.x * blockDim.x) g_v[k] = 0.f;
}

// ---- helpers --------------------------------------------------------------
__device__ __forceinline__ void cp16(float4* dst, const void* src) {
    unsigned s = (unsigned)__cvta_generic_to_shared(dst);
    asm volatile("cp.async.cg.shared.global [%0], [%1], 16;" :: "r"(s), "l"(src));
}
__device__ __forceinline__ void cp_commit() {
    asm volatile("cp.async.commit_group;" ::: "memory");
}
template <int N>
__device__ __forceinline__ void cp_wait() {
    asm volatile("cp.async.wait_group %0;" :: "n"(N) : "memory");
}
__device__ __forceinline__ void fma2(unsigned long long& d,
                                     unsigned long long a, unsigned long long b) {
    asm volatile("fma.rn.f32x2 %0, %1, %2, %3;" : "=l"(d) : "l"(a), "l"(b), "l"(d));
}
__device__ __forceinline__ unsigned long long mul2(unsigned long long a,
                                                   unsigned long long b) {
    unsigned long long d;
    asm("mul.rn.f32x2 %0, %1, %2;" : "=l"(d) : "l"(a), "l"(b));
    return d;
}
__device__ __forceinline__ float hsum(unsigned long long u) {
    float lo, hi;
    asm("mov.b64 {%0,%1}, %2;" : "=f"(lo), "=f"(hi) : "l"(u));
    return lo + hi;
}
// per-stream sync (named barrier, 128 threads)
__device__ __forceinline__ void sg_sync(int sid) {
    asm volatile("bar.sync %0, 128;" :: "r"(1 + sid) : "memory");
}

// Distributed per-stream grid barrier.
__device__ __forceinline__ void bar_arrive(int s, int wtid) {
    __threadfence();
    sg_sync(s);
    if (wtid == 0)
        atomicAdd(&g_barArr[s][(blockIdx.x & (NBAR - 1)) * BARSTRIDE], 1u);
}
__device__ __forceinline__ void bar_wait(int s, unsigned target8, int wtid) {
    if (wtid < NBAR) {
        unsigned v;
        do {
            asm volatile("ld.global.acquire.gpu.u32 %0, [%1];"
                         : "=r"(v) : "l"(&g_barArr[s][wtid * BARSTRIDE]));
        } while (v < target8);
    }
    sg_sync(s);
}

// Stage one 16-row x 64-granule(16B) chunk: 128 threads, 8 cp16 each.
__device__ __forceinline__ void stage16(float4* __restrict__ dst,
                                        const char* __restrict__ gbase,
                                        size_t rstrideB, int rp, int kk) {
#pragma unroll
    for (int i = 0; i < 8; ++i) {
        int rs = rp + i * 2;
        cp16(dst + rs * 64 + (kk ^ (rs & 7)),
             gbase + (size_t)rs * rstrideB + kk * 16);
    }
    cp_commit();
}

// 12-output chunk dot: 4 gate + 4 core + 4 tau. ws = weight granule stride.
template <bool SCALE>
__device__ __forceinline__ void dot12(const ulonglong2* __restrict__ sp, int sw,
                                      int ks, int goff,
                                      const ulonglong2* __restrict__ wg,
                                      const ulonglong2* __restrict__ wc,
                                      const ulonglong2* __restrict__ wt,
                                      int ws, unsigned long long sc,
                                      unsigned long long acc[12]) {
#pragma unroll
    for (int j = 0; j < 8; ++j) {
        int l = j * 8 + ks;
        ulonglong2 a = sp[l ^ sw];
        if (SCALE) { a.x = mul2(a.x, sc); a.y = mul2(a.y, sc); }
        int wi = goff + l;
#pragma unroll
        for (int cc = 0; cc < 4; ++cc) {
            ulonglong2 g = wg[cc * ws + wi];
            fma2(acc[cc], a.x, g.x); fma2(acc[cc], a.y, g.y);
            ulonglong2 c = wc[cc * ws + wi];
            fma2(acc[4 + cc], a.x, c.x); fma2(acc[4 + cc], a.y, c.y);
            ulonglong2 t2 = wt[cc * ws + wi];
            fma2(acc[8 + cc], a.x, t2.x); fma2(acc[8 + cc], a.y, t2.y);
        }
    }
}

// Generic 4-col dot (phases C/D), weight col stride 128 granules.
__device__ __forceinline__ void dot4(const ulonglong2* __restrict__ sp, int sw,
                                     int ks, int goff,
                                     const ulonglong2* __restrict__ w,
                                     unsigned long long acc[4][2]) {
#pragma unroll
    for (int j = 0; j < 8; ++j) {
        int l = j * 8 + ks;
        ulonglong2 a = sp[l ^ sw];
        int wi = goff + l;
#pragma unroll
        for (int cc = 0; cc < 4; ++cc) {
            ulonglong2 ww = w[cc * 128 + wi];
            fma2(acc[cc][0], a.x, ww.x);
            fma2(acc[cc][1], a.y, ww.y);
        }
    }
}

__global__ void __launch_bounds__(NTHR, 1)
ctlnn_main(const float* __restrict__ x,
           const float* __restrict__ Wm,  const float* __restrict__ bm,
           const float* __restrict__ Wf1, const float* __restrict__ bf1,
           const float* __restrict__ Wf2, const float* __restrict__ bf2,
           const float* __restrict__ Wt,  const float* __restrict__ bt,
           const float* __restrict__ gamma, const float* __restrict__ beta,
           float* __restrict__ out) {
    extern __shared__ __align__(16) float sm[];
    const int tid = threadIdx.x;
    const int bid = blockIdx.x;
    const int cbase = bid * 4;

    // ---- one-time weight slice load (whole CTA) ----
    for (int idx = tid; idx < 8 * 256; idx += NTHR) {    // Wm x-rows
        int c = idx >> 8, k = idx & 255;
        int srccol = (c < 4) ? (cbase + c) : (512 + cbase + (c - 4));
        sm[OFF_WMX + idx] = Wm[k * 1024 + srccol];
    }
    for (int idx = tid; idx < 8 * 512; idx += NTHR) {    // Wm h-rows * gamma
        int c = idx >> 9, k = idx & 511;
        int srccol = (c < 4) ? (cbase + c) : (512 + cbase + (c - 4));
        sm[OFF_WMV + idx] = Wm[(256 + k) * 1024 + srccol] * gamma[k];
    }
    for (int idx = tid; idx < 4 * 512; idx += NTHR) {
        int c = idx >> 9, k = idx & 511;
        int col = cbase + c;
        sm[OFF_WF1 + idx] = Wf1[k * 512 + col];
        sm[OFF_WF2 + idx] = Wf2[k * 512 + col];
    }
    for (int idx = tid; idx < 4 * 256; idx += NTHR)      // zero state blocks
        sm[OFF_ST + idx] = 0.f;
    if (tid < 4) {
        int col = cbase + tid;
        sm[OFF_B +  0 + tid] = bm[col];
        sm[OFF_B +  4 + tid] = bm[512 + col];
        sm[OFF_B + 12 + tid] = bf1[col];
        sm[OFF_B + 16 + tid] = bf2[col];
        sm[OFF_B + 20 + tid] = gamma[col];
        sm[OFF_B + 24 + tid] = beta[col];
    }
    {   // Bsum/Gsum for the 8 A-columns (gate 0..3, core 4..7)
        int w = tid >> 5, lane = tid & 31;
        if (w < 8) {
            int srccol = (w < 4) ? (cbase + w) : (512 + cbase + (w - 4));
            float sb = 0.f, sg = 0.f;
            for (int k = lane; k < 512; k += 32) {
                float wv = Wm[(256 + k) * 1024 + srccol];
                sb += beta[k] * wv;
                sg += gamma[k] * wv;
            }
#pragma unroll
            for (int o = 16; o; o >>= 1) {
                sb += __shfl_xor_sync(~0u, sb, o);
                sg += __shfl_xor_sync(~0u, sg, o);
            }
            if (lane == 0) { sm[OFF_B + 28 + w] = sb; sm[OFF_B + 36 + w] = sg; }
        }
    }
    __syncthreads();
    // ---- tau fold: WfX = WmX_core@Wt, WfV = WmV_core@Wt (gamma-folded) ----
    {
        float* WtS = sm + OFF_STAGE;            // 4 x 512 [c][j]
        float* Tm  = sm + OFF_STAGE + 2048;     // 24 x 512 tile
        for (int idx = tid; idx < 4 * 512; idx += NTHR) {
            int c = idx >> 9, j = idx & 511;
            WtS[idx] = Wt[j * 512 + cbase + c];
        }
        __syncthreads();
        for (int tile = 0; tile < 32; ++tile) {
            int k0 = tile * 24;
            for (int idx = tid; idx < 24 * 128; idx += NTHR) {
                int row = idx >> 7, jj = idx & 127;
                reinterpret_cast<float4*>(Tm)[row * 128 + jj] =
                    __ldg(reinterpret_cast<const float4*>(
                        Wm + (size_t)(k0 + row) * 1024 + 512) + jj);
            }
            __syncthreads();
            int row = tid >> 2, c = tid & 3;
            if (row < 24) {
                const float4* tm = reinterpret_cast<const float4*>(Tm) + row * 128;
                const float4* wt4 = reinterpret_cast<const float4*>(WtS) + c * 128;
                float s = 0.f;
                for (int jj = 0; jj < 128; ++jj) {
                    float4 a = tm[jj], b = wt4[jj];
                    s += a.x * b.x + a.y * b.y + a.z * b.z + a.w * b.w;
                }
                int k = k0 + row;
                if (k < 256) sm[OFF_WFX + c * 256 + k] = s;
                else         sm[OFF_WFV + c * 512 + (k - 256)] = s;   // raw
            }
            __syncthreads();
        }
        int w = tid >> 5, lane = tid & 31;
        if (w >= 8 && w < 12) {             // BsumT/GsumT for c = w-8
            int c = w - 8;
            float sb = 0.f, sg = 0.f;
            for (int k = lane; k < 512; k += 32) {
                float raw = sm[OFF_WFV + c * 512 + k];
                sb += beta[k] * raw;
                sg += gamma[k] * raw;
            }
#pragma unroll
            for (int o = 16; o; o >>= 1) {
                sb += __shfl_xor_sync(~0u, sb, o);
                sg += __shfl_xor_sync(~0u, sg, o);
            }
            if (lane == 0) { sm[OFF_B + 44 + c] = sb; sm[OFF_B + 48 + c] = sg; }
        } else if (w >= 12) {               // tau const C0 for c = w-12
            int c = w - 12;
            float s = 0.f;
            for (int j = lane; j < 512; j += 32)
                s += bm[512 + j] * WtS[c * 512 + j];
#pragma unroll
            for (int o = 16; o; o >>= 1)
                s += __shfl_xor_sync(~0u, s, o);
            if (lane == 0) sm[OFF_B + 8 + c] = s + bt[cbase + c];
        }
        __syncthreads();
        for (int idx = tid; idx < 4 * 512; idx += NTHR)   // gamma-fold WFV
            sm[OFF_WFV + idx] *= gamma[idx & 511];
        __syncthreads();
    }

    // ---------------- per-stream state ----------------
    const int sid  = tid >> 7;          // stream 0..3
    const int wtid = tid & 127;
    const int r    = wtid & 15;         // local row
    const int ks   = wtid >> 4;         // K-slot (0..7)
    const int sw   = r & 7;
    const int rp   = wtid >> 6;         // staging row phase (0..1)
    const int kk   = wtid & 63;         // staging granule
    const int gR   = sid * 16 + r;      // global batch row
    const int ec   = wtid >> 4;         // epilogue item (= ks)
    const int ecol = ec & 3;            // epilogue column

    float4* bufA = reinterpret_cast<float4*>(sm + OFF_STAGE) + sid * 2048;
    float4* bufB = bufA + 1024;
    float4* red4 = reinterpret_cast<float4*>(sm + OFF_RED) + sid * 384;
    float* st      = sm + OFF_ST + sid * 256;
    float* st_rstd = st;          // 16
    float* st_mr   = st + 16;     // 16
    float* st_dtT  = st + 32;     // 64
    float* st_h    = st + 96;     // 64
    float* st_v    = st + 160;    // 64

    const ulonglong2* WMXg = reinterpret_cast<const ulonglong2*>(sm + OFF_WMX);
    const ulonglong2* WMXc = WMXg + 4 * 64;
    const ulonglong2* WFXu = reinterpret_cast<const ulonglong2*>(sm + OFF_WFX);
    const ulonglong2* WMVg = reinterpret_cast<const ulonglong2*>(sm + OFF_WMV);
    const ulonglong2* WMVc = WMVg + 4 * 128;
    const ulonglong2* WFVu = reinterpret_cast<const ulonglong2*>(sm + OFF_WFV);
    const ulonglong2* WF1u = reinterpret_cast<const ulonglong2*>(sm + OFF_WF1);
    const ulonglong2* WF2u = reinterpret_cast<const ulonglong2*>(sm + OFF_WF2);

    const char* xbase = (const char*)(x + (size_t)sid * 16 * Tt * DIN);
    const char* vbase = (const char*)(g_v  + (size_t)sid * 16 * Hh);
    const char* zbase = (const char*)(g_z  + (size_t)sid * 16 * Hh);
    const char* abase = (const char*)(g_a1 + (size_t)sid * 16 * Hh);

    unsigned bar_t = 0;

    // prefetch x(t=0) into bufA
    stage16(bufA, xbase, (size_t)Tt * DIN * 4, rp, kk);

    // ---- cascade start: stream s waits for stream s-1's phase A of t=0 ----
    if (sid > 0) {
        if (wtid < NBAR) {
            unsigned v;
            do {
                asm volatile("ld.global.acquire.gpu.u32 %0, [%1];"
                             : "=r"(v) : "l"(&g_barArr[sid - 1][wtid * BARSTRIDE]));
            } while (v < 8);
        }
        sg_sync(sid);
    }

    for (int t = 0; t < Tt; ++t) {
        const int par = t & 1;

        // ============ PHASE A (12 outputs; LN + tau folded) ================
        unsigned long long acc[12] = {};
        cp_wait<0>(); sg_sync(sid);                        // x(t) ready (bufA)
        dot12<false>(reinterpret_cast<const ulonglong2*>(bufA) + r * 64, sw,
                     ks, 0, WMXg, WMXc, WFXu, 64, 0ull, acc);
        bar_wait(sid, bar_t, wtid);                        // hidden by x-dot
        stage16(bufB, vbase, Hh * 4, rp, kk);              // v0 -> B
        stage16(bufA, vbase + 1024, Hh * 4, rp, kk);       // v1 -> A
        // finalize step t-1 (distributed: 64 threads, (r, ecol))
        if (t > 0) {
            if (ec < 4) {
                int pp = (t - 1) & 1;
                float s = __ldcg(&g_rs[pp * 64 + gR]);
                float q = __ldcg(&g_rq[pp * 64 + gR]);
                float muv = s * (1.f / 512.f);
                float var = q * (1.f / 512.f) - muv * muv;
                float rstdv = rsqrtf(var + EPSc);
                float hn = (st_v[r * 4 + ecol] - muv) * rstdv
                           * sm[OFF_B + 20 + ecol] + sm[OFF_B + 24 + ecol];
                out[((size_t)gR * Tt + (t - 1)) * Hh + cbase + ecol] = hn;
                st_h[r * 4 + ecol] = hn;
                if (ecol == 0) { st_rstd[r] = rstdv; st_mr[r] = muv * rstdv; }
            }
        }
        cp_wait<1>(); sg_sync(sid);                        // v0 ready, rstd vis
        unsigned long long rstd2;
        {
            float rv = st_rstd[r];
            asm("mov.b64 %0, {%1, %1};" : "=l"(rstd2) : "f"(rv));
        }
        dot12<true>(reinterpret_cast<const ulonglong2*>(bufB) + r * 64, sw,
                    ks, 0, WMVg, WMVc, WFVu, 128, rstd2, acc);
        cp_wait<0>(); sg_sync(sid);                        // v1 ready
        dot12<true>(reinterpret_cast<const ulonglong2*>(bufA) + r * 64, sw,
                    ks, 64, WMVg, WMVc, WFVu, 128, rstd2, acc);
        {
            float4* rA = red4 + wtid * 3;
            rA[0] = make_float4(hsum(acc[0]), hsum(acc[1]), hsum(acc[2]), hsum(acc[3]));
            rA[1] = make_float4(hsum(acc[4]), hsum(acc[5]), hsum(acc[6]), hsum(acc[7]));
            rA[2] = make_float4(hsum(acc[8]), hsum(acc[9]), hsum(acc[10]), hsum(acc[11]));
        }
        sg_sync(sid);
        // distributed epilogue: 128 threads = 16 rows x 8 items (4 z + 4 tau)
        {
            float mr = st_mr[r];
            if (ec < 4) {               // z for column ecol
                float G = 0.f, Cv = 0.f;
#pragma unroll
                for (int k = 0; k < 8; ++k) {
                    const float* p = (const float*)(red4 + (r + 16 * k) * 3);
                    G  += p[ecol];
                    Cv += p[4 + ecol];
                }
                float gv = G  + sm[OFF_B + ecol];
                float cv = Cv + sm[OFF_B + 4 + ecol];
                if (t > 0) {
                    gv += sm[OFF_B + 28 + ecol]     - mr * sm[OFF_B + 36 + ecol];
                    cv += sm[OFF_B + 28 + 4 + ecol] - mr * sm[OFF_B + 36 + 4 + ecol];
                }
                float sg = 1.f / (1.f + expf(-gv));
                g_z[gR * Hh + cbase + ecol] = sg * tanhf(cv);
            } else {                    // tau for column ecol
                float T = 0.f;
#pragma unroll
                for (int k = 0; k < 8; ++k) {
                    const float* p = (const float*)(red4 + (r + 16 * k) * 3);
                    T += p[8 + ecol];
                }
                float tl = T + sm[OFF_B + 8 + ecol];
                if (t > 0)
                    tl += sm[OFF_B + 44 + ecol] - mr * sm[OFF_B + 48 + ecol];
                float spv = (tl > 20.f) ? tl : log1pf(expf(tl));
                st_dtT[r * 4 + ecol] = DTc / (spv + 1e-6f);
            }
        }
        bar_t += 8;
        bar_arrive(sid, wtid);
        bar_wait(sid, bar_t, wtid);
        if (bid == 0 && wtid < 32) {    // zero LN accs parity par^1 (own rows)
            if (wtid < 16) g_rs[(par ^ 1) * 64 + sid * 16 + wtid] = 0.f;
            else           g_rq[(par ^ 1) * 64 + sid * 16 + (wtid - 16)] = 0.f;
        }

        // ============ PHASE C: a1 = silu(z@Wf1 + bf1) ======================
        stage16(bufA, zbase,        Hh * 4, rp, kk);
        stage16(bufB, zbase + 1024, Hh * 4, rp, kk);
        unsigned long long af[4][2] = {};
        cp_wait<1>(); sg_sync(sid);                        // z0 ready
        dot4(reinterpret_cast<const ulonglong2*>(bufA) + r * 64, sw, ks, 0,
             WF1u, af);
        cp_wait<0>(); sg_sync(sid);                        // z1 ready
        dot4(reinterpret_cast<const ulonglong2*>(bufB) + r * 64, sw, ks, 64,
             WF1u, af);
        red4[wtid] = make_float4(hsum(af[0][0]) + hsum(af[0][1]),
                                 hsum(af[1][0]) + hsum(af[1][1]),
                                 hsum(af[2][0]) + hsum(af[2][1]),
                                 hsum(af[3][0]) + hsum(af[3][1]));
        sg_sync(sid);
        if (ec < 4) {                   // 64 threads: a1[r, ecol]
            float F = 0.f;
#pragma unroll
            for (int k = 0; k < 8; ++k)
                F += ((const float*)(red4 + (r + 16 * k)))[ecol];
            float f1 = F + sm[OFF_B + 12 + ecol];
            g_a1[gR * Hh + cbase + ecol] = f1 / (1.f + expf(-f1));
        }
        bar_t += 8;
        bar_arrive(sid, wtid);
        bar_wait(sid, bar_t, wtid);

        // ===== PHASE D: f = a1@Wf2 + bf2; v = h + dt/tau * f ===============
        stage16(bufA, abase,        Hh * 4, rp, kk);
        stage16(bufB, abase + 1024, Hh * 4, rp, kk);
        unsigned long long ao[4][2] = {};
        cp_wait<1>(); sg_sync(sid);                        // a1_0 ready
        dot4(reinterpret_cast<const ulonglong2*>(bufA) + r * 64, sw, ks, 0,
             WF2u, ao);
        sg_sync(sid);
        if (t + 1 < Tt) {                                  // x(t+1) -> A
            stage16(bufA, xbase + (size_t)(t + 1) * DIN * 4,
                    (size_t)Tt * DIN * 4, rp, kk);
            cp_wait<1>();
        } else {
            cp_wait<0>();
        }
        sg_sync(sid);                                      // a1_1 ready
        dot4(reinterpret_cast<const ulonglong2*>(bufB) + r * 64, sw, ks, 64,
             WF2u, ao);
        red4[wtid] = make_float4(hsum(ao[0][0]) + hsum(ao[0][1]),
                                 hsum(ao[1][0]) + hsum(ao[1][1]),
                                 hsum(ao[2][0]) + hsum(ao[2][1]),
                                 hsum(ao[3][0]) + hsum(ao[3][1]));
        sg_sync(sid);
        if (ec < 4) {                   // 64 threads: v[r, ecol]
            float F = 0.f;
#pragma unroll
            for (int k = 0; k < 8; ++k)
                F += ((const float*)(red4 + (r + 16 * k)))[ecol];
            float f = F + sm[OFF_B + 16 + ecol];
            float v = st_h[r * 4 + ecol] + st_dtT[r * 4 + ecol] * f;
            g_v[gR * Hh + cbase + ecol] = v;
            st_v[r * 4 + ecol] = v;
        }
        sg_sync(sid);
        if (wtid < 16) {                // one atomic pair per (CTA, row)
            float s0 = st_v[wtid * 4 + 0] + st_v[wtid * 4 + 1]
                     + st_v[wtid * 4 + 2] + st_v[wtid * 4 + 3];
            float q0 = st_v[wtid * 4 + 0] * st_v[wtid * 4 + 0]
                     + st_v[wtid * 4 + 1] * st_v[wtid * 4 + 1]
                     + st_v[wtid * 4 + 2] * st_v[wtid * 4 + 2]
                     + st_v[wtid * 4 + 3] * st_v[wtid * 4 + 3];
            atomicAdd(&g_rs[par * 64 + sid * 16 + wtid], s0);
            atomicAdd(&g_rq[par * 64 + sid * 16 + wtid], q0);
        }
        bar_arrive(sid, wtid);          // split: wait in next phase A
        bar_t += 8;
    }

    bar_wait(sid, bar_t, wtid);
    // final output row (t = Tt-1), distributed
    if (ec < 4) {
        int pp = (Tt - 1) & 1;
        float s = __ldcg(&g_rs[pp * 64 + gR]);
        float q = __ldcg(&g_rq[pp * 64 + gR]);
        float muv = s * (1.f / 512.f);
        float var = q * (1.f / 512.f) - muv * muv;
        float rstdv = rsqrtf(var + EPSc);
        float hn = (st_v[r * 4 + ecol] - muv) * rstdv
                   * sm[OFF_B + 20 + ecol] + sm[OFF_B + 24 + ecol];
        out[((size_t)gR * Tt + (Tt - 1)) * Hh + cbase + ecol] = hn;
    }
}

extern "C" void kernel_launch(void* const* d_in, const int* in_sizes, int n_in,
                              void* d_out, int out_size) {
    const float* x     = (const float*)d_in[0];
    const float* Wm    = (const float*)d_in[1];
    const float* bm    = (const float*)d_in[2];
    const float* Wf1   = (const float*)d_in[3];
    const float* bf1   = (const float*)d_in[4];
    const float* Wf2   = (const float*)d_in[5];
    const float* bf2   = (const float*)d_in[6];
    const float* Wt    = (const float*)d_in[7];
    const float* bt    = (const float*)d_in[8];
    const float* gamma = (const float*)d_in[9];
    const float* beta  = (const float*)d_in[10];
    float* out = (float*)d_out;

    cudaFuncSetAttribute(ctlnn_main, cudaFuncAttributeMaxDynamicSharedMemorySize,
                         SMEM_FLOATS * sizeof(float));

    ctlnn_reset<<<64, 256>>>();
    ctlnn_main<<<NCTA, NTHR, SMEM_FLOATS * sizeof(float)>>>(
        x, Wm, bm, Wf1, bf1, Wf2, bf2, Wt, bt, gamma, beta, out);
}